// round 16
// baseline (speedup 1.0000x reference)
#include <cuda_runtime.h>
#include <cuda_bf16.h>
#include <math.h>

typedef unsigned long long ull;
typedef unsigned uint32;

// Problem dims
#define BB 64
#define TT 200
#define NS 1024
#define CN 256
#define HH 1024
#define G4 4096
#define MROWS (BB*TT)   // 12800
#define MPAD 12928

// Persistent-kernel config
#define NCTA 128
#define WHP 1032                 // Whh staging pitch (bf16)
#define PSTR 40                  // partial-sum row stride (floats)
#define SMEM_LSTM 132096         // max(whh staging 132096, partials 81920)
#define FRAGW 32768

// ---- scratch globals ----
__device__ float g_G[(size_t)MROWS * G4];
__device__ float g_nextkc[MROWS * CN];
__device__ uint32 g_hfrag[2][2][FRAGW];
__device__ uint32 g_flags[NCTA];          // per-CTA barrier flags

// mask-sort tables
__device__ int g_perm[MROWS];
__device__ int g_inv[MPAD];
__device__ int g_n1pad;

// bf16 split planes
__device__ __nv_bfloat16 g_pch[(size_t)MPAD * CN], g_pcl[(size_t)MPAD * CN];
__device__ __nv_bfloat16 g_hsh[(size_t)MROWS * HH], g_hsl[(size_t)MROWS * HH];
__device__ __nv_bfloat16 g_wkh[CN * NS],  g_wkl[CN * NS];
__device__ __nv_bfloat16 g_wih[G4 * 2 * CN], g_wil[G4 * 2 * CN];
__device__ __nv_bfloat16 g_wsh[CN * HH],  g_wsl[CN * HH];

// ---- helpers ----
__device__ __forceinline__ void splitbf(float v, __nv_bfloat16& h, __nv_bfloat16& l) {
    h = __float2bfloat16_rn(v);
    l = __float2bfloat16_rn(v - __bfloat162float(h));
}
__device__ __forceinline__ uint32 smaddr(const void* p) {
    return (uint32)__cvta_generic_to_shared(p);
}
__device__ __forceinline__ void ldm4(uint32* r, uint32 addr) {
    asm volatile("ldmatrix.sync.aligned.m8n8.x4.shared.b16 {%0,%1,%2,%3}, [%4];"
                 : "=r"(r[0]), "=r"(r[1]), "=r"(r[2]), "=r"(r[3]) : "r"(addr));
}
__device__ __forceinline__ void mma16816(float* c, const uint32* a, const uint32* b) {
    asm volatile("mma.sync.aligned.m16n8k16.row.col.f32.bf16.bf16.f32 "
                 "{%0,%1,%2,%3},{%4,%5,%6,%7},{%8,%9},{%0,%1,%2,%3};"
                 : "+f"(c[0]), "+f"(c[1]), "+f"(c[2]), "+f"(c[3])
                 : "r"(a[0]), "r"(a[1]), "r"(a[2]), "r"(a[3]), "r"(b[0]), "r"(b[1]));
}

__global__ void init_misc() {
    int i = blockIdx.x * blockDim.x + threadIdx.x;
    if (i < 2 * FRAGW) ((uint32*)g_hfrag[0])[i] = 0u;
    if (i < NCTA) g_flags[i] = 0u;
}

// mask-sort: stable partition rows by result==1, padded to 128-row boundary
__global__ void build_perm(const int* __restrict__ result) {
    __shared__ int s1[256];
    __shared__ int p1[256], p0[256];
    __shared__ int n1pad_s;
    int tid = threadIdx.x;
    for (int r = tid; r < MPAD; r += 256) g_inv[r] = -1;
    int base = tid * 50;
    int c1 = 0;
    for (int i = 0; i < 50; i++) c1 += (result[base + i] == 1);
    s1[tid] = c1;
    __syncthreads();
    if (tid == 0) {
        int a1 = 0, a0 = 0;
        for (int i = 0; i < 256; i++) {
            p1[i] = a1; a1 += s1[i];
            p0[i] = a0; a0 += 50 - s1[i];
        }
        n1pad_s = (a1 + 127) & ~127;
        g_n1pad = n1pad_s;
    }
    __syncthreads();
    int r1 = p1[tid], r0 = n1pad_s + p0[tid];
    for (int i = 0; i < 50; i++) {
        int m = base + i;
        int p = (result[m] == 1) ? r1++ : r0++;
        g_perm[m] = p;
        g_inv[p] = m;
    }
}

// fp32 -> (hi, lo) bf16 planes (weights only)
__global__ void cvt_split(const float* __restrict__ src,
                          __nv_bfloat16* __restrict__ hi,
                          __nv_bfloat16* __restrict__ lo, int n4) {
    int i = blockIdx.x * blockDim.x + threadIdx.x;
    if (i >= n4) return;
    float4 v = ((const float4*)src)[i];
    __nv_bfloat16 h, l;
    splitbf(v.x, h, l); hi[4*i+0] = h; lo[4*i+0] = l;
    splitbf(v.y, h, l); hi[4*i+1] = h; lo[4*i+1] = l;
    splitbf(v.z, h, l); hi[4*i+2] = h; lo[4*i+2] = l;
    splitbf(v.w, h, l); hi[4*i+3] = h; lo[4*i+3] = l;
}

// ---------------------------------------------------------------------------
// bf16-split tensor-core GEMM (R13 version — measured fastest).
// afp32: A fp32, split fused into staging.
// mode 0: C -> g_nextkc. mode 1: kc -> permuted planes. mode 2: permuted kc
// planes @ W_ih half (per-tile), scatter to g_G. mode 3: hseq planes -> Cext.
// ---------------------------------------------------------------------------
__global__ __launch_bounds__(256, 1) void mma_gemm(
        const void* __restrict__ Ah_, const __nv_bfloat16* __restrict__ Al_,
        const __nv_bfloat16* __restrict__ Bh_, const __nv_bfloat16* __restrict__ Bl_,
        const float* __restrict__ bias, const float* __restrict__ bias2,
        float* __restrict__ Cext, int K, int lda, int ldb, int mode, int afp32) {
    __shared__ __nv_bfloat16 sAh[128][40], sAl[128][40];
    __shared__ __nv_bfloat16 sBh[128][40], sBl[128][40];

    const int tid = threadIdx.x;
    const int m0 = blockIdx.y * 128, n0 = blockIdx.x * 128;

    const __nv_bfloat16* Ah = (const __nv_bfloat16*)Ah_;
    const __nv_bfloat16* Al = Al_;
    const float* Af = (const float*)Ah_;
    const __nv_bfloat16* Bh = Bh_;
    const __nv_bfloat16* Bl = Bl_;
    if (mode == 2) {
        Ah = g_pch; Al = g_pcl;
        int bofs = (m0 < g_n1pad) ? 0 : 256;
        Bh += bofs; Bl += bofs;
    } else if (mode == 3) {
        Ah = g_hsh; Al = g_hsl;
    }

    const int warp = tid >> 5, lane = tid & 31;
    const int wm = warp >> 1, wn = warp & 1;
    const int lrow = tid >> 1;
    const int lcol = (tid & 1) * 16;

    float acc[2][8][4];
#pragma unroll
    for (int i = 0; i < 2; i++)
#pragma unroll
        for (int j = 0; j < 8; j++)
#pragma unroll
            for (int q = 0; q < 4; q++) acc[i][j][q] = 0.f;

    for (int k0 = 0; k0 < K; k0 += 32) {
        uint4 bh0 = *(const uint4*)&Bh[(size_t)(n0 + lrow) * ldb + k0 + lcol];
        uint4 bh1 = *(const uint4*)&Bh[(size_t)(n0 + lrow) * ldb + k0 + lcol + 8];
        uint4 bl0 = *(const uint4*)&Bl[(size_t)(n0 + lrow) * ldb + k0 + lcol];
        uint4 bl1 = *(const uint4*)&Bl[(size_t)(n0 + lrow) * ldb + k0 + lcol + 8];
        if (afp32) {
            float4 f[4];
#pragma unroll
            for (int q = 0; q < 4; q++)
                f[q] = *(const float4*)&Af[(size_t)(m0 + lrow) * lda + k0 + lcol + q * 4];
            __syncthreads();
#pragma unroll
            for (int q = 0; q < 4; q++) {
                float vv[4] = {f[q].x, f[q].y, f[q].z, f[q].w};
#pragma unroll
                for (int e = 0; e < 4; e++) {
                    __nv_bfloat16 h, l;
                    splitbf(vv[e], h, l);
                    sAh[lrow][lcol + q * 4 + e] = h;
                    sAl[lrow][lcol + q * 4 + e] = l;
                }
            }
        } else {
            uint4 ah0 = *(const uint4*)&Ah[(size_t)(m0 + lrow) * lda + k0 + lcol];
            uint4 ah1 = *(const uint4*)&Ah[(size_t)(m0 + lrow) * lda + k0 + lcol + 8];
            uint4 al0 = *(const uint4*)&Al[(size_t)(m0 + lrow) * lda + k0 + lcol];
            uint4 al1 = *(const uint4*)&Al[(size_t)(m0 + lrow) * lda + k0 + lcol + 8];
            __syncthreads();
            *(uint4*)&sAh[lrow][lcol] = ah0; *(uint4*)&sAh[lrow][lcol + 8] = ah1;
            *(uint4*)&sAl[lrow][lcol] = al0; *(uint4*)&sAl[lrow][lcol + 8] = al1;
        }
        *(uint4*)&sBh[lrow][lcol] = bh0; *(uint4*)&sBh[lrow][lcol + 8] = bh1;
        *(uint4*)&sBl[lrow][lcol] = bl0; *(uint4*)&sBl[lrow][lcol + 8] = bl1;
        __syncthreads();

#pragma unroll
        for (int ks = 0; ks < 32; ks += 16) {
            uint32 aH[2][4], aL[2][4];
#pragma unroll
            for (int mt = 0; mt < 2; mt++) {
                int row = wm * 32 + mt * 16 + (lane & 15);
                int col = ks + (lane >> 4) * 8;
                ldm4(aH[mt], smaddr(&sAh[row][col]));
                ldm4(aL[mt], smaddr(&sAl[row][col]));
            }
            uint32 bH[8][2], bL[8][2];
#pragma unroll
            for (int np = 0; np < 4; np++) {
                int row = wn * 64 + np * 16 + (lane & 7) + ((lane >> 4) & 1) * 8;
                int col = ks + ((lane >> 3) & 1) * 8;
                uint32 t4[4];
                ldm4(t4, smaddr(&sBh[row][col]));
                bH[2*np][0] = t4[0]; bH[2*np][1] = t4[1];
                bH[2*np+1][0] = t4[2]; bH[2*np+1][1] = t4[3];
                ldm4(t4, smaddr(&sBl[row][col]));
                bL[2*np][0] = t4[0]; bL[2*np][1] = t4[1];
                bL[2*np+1][0] = t4[2]; bL[2*np+1][1] = t4[3];
            }
#pragma unroll
            for (int mt = 0; mt < 2; mt++)
#pragma unroll
                for (int nt = 0; nt < 8; nt++) {
                    mma16816(acc[mt][nt], aH[mt], bH[nt]);
                    mma16816(acc[mt][nt], aH[mt], bL[nt]);
                    mma16816(acc[mt][nt], aL[mt], bH[nt]);
                }
        }
    }

#pragma unroll
    for (int mt = 0; mt < 2; mt++) {
#pragma unroll
        for (int nt = 0; nt < 8; nt++) {
#pragma unroll
            for (int q = 0; q < 4; q++) {
                int m = m0 + wm * 32 + mt * 16 + (lane >> 2) + (q >> 1) * 8;
                int n = n0 + wn * 64 + nt * 8 + 2 * (lane & 3) + (q & 1);
                float v = acc[mt][nt][q] + bias[n];
                if (bias2) v += bias2[n];
                if (mode == 0) {
                    g_nextkc[m * CN + n] = v;
                } else if (mode == 1) {
                    int pr = g_perm[m];
                    __nv_bfloat16 h, l;
                    splitbf(v, h, l);
                    g_pch[(size_t)pr * CN + n] = h;
                    g_pcl[(size_t)pr * CN + n] = l;
                } else if (mode == 2) {
                    int orig = g_inv[m];
                    if (orig >= 0) {
                        int b = orig / TT, t = orig - b * TT;
                        g_G[((size_t)t * BB + b) * G4 + n] = v;
                    }
                } else {
                    Cext[(size_t)m * CN + n] = v;
                }
            }
        }
    }
}

// ---------------------------------------------------------------------------
// Flag-array grid barrier: per-CTA release-store of step number; warp 0 polls
// all 128 flags with 32 relaxed v4 loads + ballot. No atomic contention.
// ---------------------------------------------------------------------------
__device__ __forceinline__ void gsync(uint32 step, int bid) {
    __syncthreads();
    if (threadIdx.x == 0) {
        asm volatile("st.release.gpu.global.u32 [%0], %1;"
                     :: "l"(&g_flags[bid]), "r"(step) : "memory");
    }
    if (threadIdx.x < 32) {
        const uint32* fp = g_flags + threadIdx.x * 4;
        for (;;) {
            uint32 v0, v1, v2, v3;
            asm volatile("ld.relaxed.gpu.global.v4.u32 {%0,%1,%2,%3}, [%4];"
                         : "=r"(v0), "=r"(v1), "=r"(v2), "=r"(v3) : "l"(fp));
            bool ok = (v0 >= step) && (v1 >= step) && (v2 >= step) && (v3 >= step);
            if (__all_sync(0xffffffffu, ok)) break;
        }
        asm volatile("fence.acq_rel.gpu;" ::: "memory");
    }
    __syncthreads();
}

// ---------------------------------------------------------------------------
// Persistent fused LSTM — register-resident W_hh fragments + pipelined A
// fragments (R13 core, measured fastest), flag-array barrier.
// ---------------------------------------------------------------------------
__global__ __launch_bounds__(256, 1) void lstm_persist(const float* __restrict__ Whh) {
    extern __shared__ char smraw[];
    __nv_bfloat16* whh_h = (__nv_bfloat16*)smraw;           // staging (init only)
    __nv_bfloat16* whh_l = whh_h + 32 * WHP;
    float* part = (float*)smraw;                             // [8][64][PSTR] after init

    const int tid = threadIdx.x, wid = tid >> 5, lane = tid & 31;
    const int jb0 = blockIdx.x * 8;

    for (int idx = tid; idx < 32 * 1024; idx += 256) {
        int c = idx >> 10, k = idx & 1023;
        int gr = ((c >> 3) << 10) + jb0 + (c & 7);
        float w = Whh[(size_t)gr * HH + k];
        __nv_bfloat16 h, l;
        splitbf(w, h, l);
        whh_h[c * WHP + k] = h;
        whh_l[c * WHP + k] = l;
    }
    __syncthreads();

    uint32 BH[8][4][2], BL[8][4][2];
#pragma unroll
    for (int kbl = 0; kbl < 8; kbl++) {
#pragma unroll
        for (int g = 0; g < 2; g++) {
            int row = g * 16 + (lane & 7) + ((lane >> 4) & 1) * 8;
            int col = (wid * 8 + kbl) * 16 + ((lane >> 3) & 1) * 8;
            uint32 t4[4];
            ldm4(t4, smaddr(&whh_h[row * WHP + col]));
            BH[kbl][2*g][0] = t4[0]; BH[kbl][2*g][1] = t4[1];
            BH[kbl][2*g+1][0] = t4[2]; BH[kbl][2*g+1][1] = t4[3];
            ldm4(t4, smaddr(&whh_l[row * WHP + col]));
            BL[kbl][2*g][0] = t4[0]; BL[kbl][2*g][1] = t4[1];
            BL[kbl][2*g+1][0] = t4[2]; BL[kbl][2*g+1][1] = t4[3];
        }
    }
    __syncthreads();

    const int gb_b = tid >> 2;
    const int gjp = tid & 3;
    const int m16w = gb_b >> 4;
    const int roww = gb_b & 15;
    const int rlw = roww & 7;
    const int regbase = (roww >> 3) + ((jb0 & 8) ? 2 : 0);
    const int k16w = jb0 >> 4;
    float cst2[2] = {0.f, 0.f};

    float gb[4][2];
    {
        const float* Gp = g_G + (size_t)gb_b * G4 + jb0 + 2 * gjp;
#pragma unroll
        for (int g = 0; g < 4; g++) {
            float2 v = __ldcg((const float2*)&Gp[g * HH]);
            gb[g][0] = v.x; gb[g][1] = v.y;
        }
    }

    for (int t = 0; t < TT; t++) {
        const uint32* fH = g_hfrag[t & 1][0];
        const uint32* fL = g_hfrag[t & 1][1];
        const int nb = (t + 1) & 1;

        float acc[4][4][4];
#pragma unroll
        for (int mf = 0; mf < 4; mf++)
#pragma unroll
            for (int nf = 0; nf < 4; nf++)
#pragma unroll
                for (int q = 0; q < 4; q++) acc[mf][nf][q] = 0.f;

        uint4 aH4[2][4], aL4[4];
        {
            const int kb = wid * 8;
#pragma unroll
            for (int mf = 0; mf < 4; mf++)
                aH4[0][mf] = __ldcg((const uint4*)&fH[((kb * 4 + mf) * 32 + lane) * 4]);
        }

#pragma unroll
        for (int kbl = 0; kbl < 8; kbl++) {
            const int cur = kbl & 1, nxt = cur ^ 1;
            const int kb = wid * 8 + kbl;
#pragma unroll
            for (int mf = 0; mf < 4; mf++)
                aL4[mf] = __ldcg((const uint4*)&fL[((kb * 4 + mf) * 32 + lane) * 4]);
            if (kbl < 7) {
#pragma unroll
                for (int mf = 0; mf < 4; mf++)
                    aH4[nxt][mf] = __ldcg((const uint4*)&fH[(((kb + 1) * 4 + mf) * 32 + lane) * 4]);
            }
#pragma unroll
            for (int mf = 0; mf < 4; mf++)
#pragma unroll
                for (int nf = 0; nf < 4; nf++) {
                    mma16816(acc[mf][nf], (const uint32*)&aH4[cur][mf], BH[kbl][nf]);
                    mma16816(acc[mf][nf], (const uint32*)&aH4[cur][mf], BL[kbl][nf]);
                }
#pragma unroll
            for (int mf = 0; mf < 4; mf++)
#pragma unroll
                for (int nf = 0; nf < 4; nf++)
                    mma16816(acc[mf][nf], (const uint32*)&aL4[mf], BH[kbl][nf]);
        }

        {
            float* pw = part + wid * (64 * PSTR);
            int rowc = lane >> 2, colc = (lane & 3) * 2;
#pragma unroll
            for (int mf = 0; mf < 4; mf++)
#pragma unroll
                for (int nf = 0; nf < 4; nf++) {
                    int n = nf * 8 + colc;
                    *(float2*)&pw[(mf * 16 + rowc) * PSTR + n] =
                        make_float2(acc[mf][nf][0], acc[mf][nf][1]);
                    *(float2*)&pw[(mf * 16 + rowc + 8) * PSTR + n] =
                        make_float2(acc[mf][nf][2], acc[mf][nf][3]);
                }
        }
        __syncthreads();

        {
            float zz[4][2];
#pragma unroll
            for (int g = 0; g < 4; g++) { zz[g][0] = 0.f; zz[g][1] = 0.f; }
#pragma unroll
            for (int w8 = 0; w8 < 8; w8++) {
                const float* pr = part + w8 * (64 * PSTR) + gb_b * PSTR + 2 * gjp;
#pragma unroll
                for (int g = 0; g < 4; g++) {
                    float2 v = *(const float2*)&pr[g * 8];
                    zz[g][0] += v.x; zz[g][1] += v.y;
                }
            }
            unsigned short hh[2], hl[2];
#pragma unroll
            for (int e = 0; e < 2; e++) {
                float pi = zz[0][e] + gb[0][e];
                float pf = zz[1][e] + gb[1][e];
                float pg = zz[2][e] + gb[2][e];
                float po = zz[3][e] + gb[3][e];
                float iv = 1.f / (1.f + expf(-pi));
                float fv = 1.f / (1.f + expf(-pf));
                float ov = 1.f / (1.f + expf(-po));
                float gv = tanhf(pg);
                cst2[e] = fv * cst2[e] + iv * gv;
                float h = ov * tanhf(cst2[e]);
                __nv_bfloat16 bh, bl;
                splitbf(h, bh, bl);
                hh[e] = __bfloat16_as_ushort(bh);
                hl[e] = __bfloat16_as_ushort(bl);
            }
            uint32 vh = (uint32)hh[0] | ((uint32)hh[1] << 16);
            uint32 vl = (uint32)hl[0] | ((uint32)hl[1] << 16);
            int idx = ((k16w * 4 + m16w) * 32 + rlw * 4 + gjp) * 4 + regbase;
            g_hfrag[nb][0][idx] = vh;
            g_hfrag[nb][1][idx] = vl;
            *(uint32*)&g_hsh[((size_t)gb_b * TT + t) * HH + jb0 + 2 * gjp] = vh;
            *(uint32*)&g_hsl[((size_t)gb_b * TT + t) * HH + jb0 + 2 * gjp] = vl;
        }

        if (t + 1 < TT) {
            const float* Gp = g_G + ((size_t)(t + 1) * BB + gb_b) * G4 + jb0 + 2 * gjp;
#pragma unroll
            for (int g = 0; g < 4; g++) {
                float2 v = __ldcg((const float2*)&Gp[g * HH]);
                gb[g][0] = v.x; gb[g][1] = v.y;
            }
        }

        gsync((uint32)(t + 1), blockIdx.x);
    }
}

// ---------------------------------------------------------------------------
__global__ void out_kernel(const float* __restrict__ Wout,
                           const float* __restrict__ bout,
                           float* __restrict__ dout) {
    int gw = (blockIdx.x * blockDim.x + threadIdx.x) >> 5;
    int lane = threadIdx.x & 31;
    if (gw >= MROWS) return;
    const float* stu = dout + MROWS + (size_t)gw * CN;
    float s = 0.f;
#pragma unroll
    for (int c = lane; c < CN; c += 32) {
        float nk = g_nextkc[gw * CN + c];
        s += (stu[c] - nk) * nk * Wout[c];
    }
#pragma unroll
    for (int o = 16; o; o >>= 1) s += __shfl_down_sync(0xffffffffu, s, o);
    if (lane == 0) dout[gw] = s + bout[0];
}

extern "C" void kernel_launch(void* const* d_in, const int* in_sizes, int n_in,
                              void* d_out, int out_size) {
    int wi = (n_in >= 14) ? 4 : 3;
    const float* q_hot   = (const float*)d_in[0];
    const int*   result  = (const int*)  d_in[1];
    const float* next_q  = (const float*)d_in[2];
    const float* W_kc    = (const float*)d_in[wi + 0];
    const float* b_kc    = (const float*)d_in[wi + 1];
    const float* W_ih    = (const float*)d_in[wi + 2];
    const float* W_hh    = (const float*)d_in[wi + 3];
    const float* b_ih    = (const float*)d_in[wi + 4];
    const float* b_hh    = (const float*)d_in[wi + 5];
    const float* W_state = (const float*)d_in[wi + 6];
    const float* b_state = (const float*)d_in[wi + 7];
    const float* W_out   = (const float*)d_in[wi + 8];
    const float* b_out   = (const float*)d_in[wi + 9];
    float* out = (float*)d_out;

    static int smem_set = 0;
    if (!smem_set) {
        cudaFuncSetAttribute(lstm_persist, cudaFuncAttributeMaxDynamicSharedMemorySize, SMEM_LSTM);
        smem_set = 1;
    }

    init_misc<<<(2 * FRAGW + 255) / 256, 256>>>();
    build_perm<<<1, 256>>>(result);

    __nv_bfloat16 *wkh, *wkl, *wih, *wil, *wsh, *wsl;
    cudaGetSymbolAddress((void**)&wkh, g_wkh); cudaGetSymbolAddress((void**)&wkl, g_wkl);
    cudaGetSymbolAddress((void**)&wih, g_wih); cudaGetSymbolAddress((void**)&wil, g_wil);
    cudaGetSymbolAddress((void**)&wsh, g_wsh); cudaGetSymbolAddress((void**)&wsl, g_wsl);

    int n4k = CN * NS / 4;
    cvt_split<<<(n4k + 255) / 256, 256>>>(W_kc, wkh, wkl, n4k);
    int n4i = G4 * 2 * CN / 4;
    cvt_split<<<(n4i + 255) / 256, 256>>>(W_ih, wih, wil, n4i);
    int n4s = CN * HH / 4;
    cvt_split<<<(n4s + 255) / 256, 256>>>(W_state, wsh, wsl, n4s);

    dim3 gk(CN / 128, MROWS / 128);       // (2, 100)
    mma_gemm<<<gk, 256>>>(q_hot, nullptr, wkh, wkl, b_kc, nullptr, nullptr,
                          NS, NS, NS, 1, 1);
    mma_gemm<<<gk, 256>>>(next_q, nullptr, wkh, wkl, b_kc, nullptr, nullptr,
                          NS, NS, NS, 0, 1);
    dim3 gg(G4 / 128, MPAD / 128);        // (32, 101)
    mma_gemm<<<gg, 256>>>(nullptr, nullptr, wih, wil, b_ih, b_hh, nullptr,
                          CN, CN, 2 * CN, 2, 0);

    lstm_persist<<<NCTA, 256, SMEM_LSTM>>>(W_hh);

    mma_gemm<<<gk, 256>>>(nullptr, nullptr, wsh, wsl, b_state, nullptr,
                          out + MROWS, HH, HH, HH, 3, 0);
    out_kernel<<<(MROWS * 32 + 255) / 256, 256>>>(W_out, b_out, out);
}

// round 17
// speedup vs baseline: 1.3438x; 1.3438x over previous
#include <cuda_runtime.h>
#include <cuda_bf16.h>
#include <math.h>

typedef unsigned long long ull;
typedef unsigned uint32;

// Problem dims
#define BB 64
#define TT 200
#define NS 1024
#define CN 256
#define HH 1024
#define G4 4096
#define MROWS (BB*TT)   // 12800
#define MPAD 12928

// Persistent-kernel config
#define NCTA 128
#define WHP 1032                 // Whh staging pitch (bf16)
#define PSTR 40                  // partial-sum row stride (floats)
#define SMEM_LSTM 132096         // max(whh staging 132096, partials 81920)
#define FRAGW 32768

// ---- scratch globals ----
__device__ float g_G[(size_t)MROWS * G4];
__device__ float g_nextkc[MROWS * CN];
__device__ uint32 g_hfrag[2][2][FRAGW];
__device__ unsigned g_barc;

// mask-sort tables
__device__ int g_perm[MROWS];
__device__ int g_inv[MPAD];
__device__ int g_n1pad;

// bf16 split planes
__device__ __nv_bfloat16 g_pch[(size_t)MPAD * CN], g_pcl[(size_t)MPAD * CN];
__device__ __nv_bfloat16 g_hsh[(size_t)MROWS * HH], g_hsl[(size_t)MROWS * HH];
__device__ __nv_bfloat16 g_wkh[CN * NS],  g_wkl[CN * NS];
__device__ __nv_bfloat16 g_wih[G4 * 2 * CN], g_wil[G4 * 2 * CN];
__device__ __nv_bfloat16 g_wsh[CN * HH],  g_wsl[CN * HH];

// ---- helpers ----
__device__ __forceinline__ void splitbf(float v, __nv_bfloat16& h, __nv_bfloat16& l) {
    h = __float2bfloat16_rn(v);
    l = __float2bfloat16_rn(v - __bfloat162float(h));
}
__device__ __forceinline__ uint32 smaddr(const void* p) {
    return (uint32)__cvta_generic_to_shared(p);
}
__device__ __forceinline__ void ldm4(uint32* r, uint32 addr) {
    asm volatile("ldmatrix.sync.aligned.m8n8.x4.shared.b16 {%0,%1,%2,%3}, [%4];"
                 : "=r"(r[0]), "=r"(r[1]), "=r"(r[2]), "=r"(r[3]) : "r"(addr));
}
__device__ __forceinline__ void mma16816(float* c, const uint32* a, const uint32* b) {
    asm volatile("mma.sync.aligned.m16n8k16.row.col.f32.bf16.bf16.f32 "
                 "{%0,%1,%2,%3},{%4,%5,%6,%7},{%8,%9},{%0,%1,%2,%3};"
                 : "+f"(c[0]), "+f"(c[1]), "+f"(c[2]), "+f"(c[3])
                 : "r"(a[0]), "r"(a[1]), "r"(a[2]), "r"(a[3]), "r"(b[0]), "r"(b[1]));
}

__global__ void init_misc() {
    int i = blockIdx.x * blockDim.x + threadIdx.x;
    if (i < 2 * FRAGW) ((uint32*)g_hfrag[0])[i] = 0u;
    if (i == 0) g_barc = 0u;
}

// mask-sort: stable partition rows by result==1, padded to 128-row boundary
__global__ void build_perm(const int* __restrict__ result) {
    __shared__ int s1[256];
    __shared__ int p1[256], p0[256];
    __shared__ int n1pad_s;
    int tid = threadIdx.x;
    for (int r = tid; r < MPAD; r += 256) g_inv[r] = -1;
    int base = tid * 50;
    int c1 = 0;
    for (int i = 0; i < 50; i++) c1 += (result[base + i] == 1);
    s1[tid] = c1;
    __syncthreads();
    if (tid == 0) {
        int a1 = 0, a0 = 0;
        for (int i = 0; i < 256; i++) {
            p1[i] = a1; a1 += s1[i];
            p0[i] = a0; a0 += 50 - s1[i];
        }
        n1pad_s = (a1 + 127) & ~127;
        g_n1pad = n1pad_s;
    }
    __syncthreads();
    int r1 = p1[tid], r0 = n1pad_s + p0[tid];
    for (int i = 0; i < 50; i++) {
        int m = base + i;
        int p = (result[m] == 1) ? r1++ : r0++;
        g_perm[m] = p;
        g_inv[p] = m;
    }
}

// fp32 -> (hi, lo) bf16 planes (weights only)
__global__ void cvt_split(const float* __restrict__ src,
                          __nv_bfloat16* __restrict__ hi,
                          __nv_bfloat16* __restrict__ lo, int n4) {
    int i = blockIdx.x * blockDim.x + threadIdx.x;
    if (i >= n4) return;
    float4 v = ((const float4*)src)[i];
    __nv_bfloat16 h, l;
    splitbf(v.x, h, l); hi[4*i+0] = h; lo[4*i+0] = l;
    splitbf(v.y, h, l); hi[4*i+1] = h; lo[4*i+1] = l;
    splitbf(v.z, h, l); hi[4*i+2] = h; lo[4*i+2] = l;
    splitbf(v.w, h, l); hi[4*i+3] = h; lo[4*i+3] = l;
}

// ---------------------------------------------------------------------------
// bf16-split tensor-core GEMM. afp32: A fp32, split fused into staging.
// mode 0: C -> g_nextkc. mode 1: kc -> permuted planes. mode 2: permuted kc
// planes @ W_ih half (per-tile), scatter to g_G. mode 3: hseq planes -> Cext.
// ---------------------------------------------------------------------------
__global__ __launch_bounds__(256, 1) void mma_gemm(
        const void* __restrict__ Ah_, const __nv_bfloat16* __restrict__ Al_,
        const __nv_bfloat16* __restrict__ Bh_, const __nv_bfloat16* __restrict__ Bl_,
        const float* __restrict__ bias, const float* __restrict__ bias2,
        float* __restrict__ Cext, int K, int lda, int ldb, int mode, int afp32) {
    __shared__ __nv_bfloat16 sAh[128][40], sAl[128][40];
    __shared__ __nv_bfloat16 sBh[128][40], sBl[128][40];

    const int tid = threadIdx.x;
    const int m0 = blockIdx.y * 128, n0 = blockIdx.x * 128;

    const __nv_bfloat16* Ah = (const __nv_bfloat16*)Ah_;
    const __nv_bfloat16* Al = Al_;
    const float* Af = (const float*)Ah_;
    const __nv_bfloat16* Bh = Bh_;
    const __nv_bfloat16* Bl = Bl_;
    if (mode == 2) {
        Ah = g_pch; Al = g_pcl;
        int bofs = (m0 < g_n1pad) ? 0 : 256;
        Bh += bofs; Bl += bofs;
    } else if (mode == 3) {
        Ah = g_hsh; Al = g_hsl;
    }

    const int warp = tid >> 5, lane = tid & 31;
    const int wm = warp >> 1, wn = warp & 1;
    const int lrow = tid >> 1;
    const int lcol = (tid & 1) * 16;

    float acc[2][8][4];
#pragma unroll
    for (int i = 0; i < 2; i++)
#pragma unroll
        for (int j = 0; j < 8; j++)
#pragma unroll
            for (int q = 0; q < 4; q++) acc[i][j][q] = 0.f;

    for (int k0 = 0; k0 < K; k0 += 32) {
        uint4 bh0 = *(const uint4*)&Bh[(size_t)(n0 + lrow) * ldb + k0 + lcol];
        uint4 bh1 = *(const uint4*)&Bh[(size_t)(n0 + lrow) * ldb + k0 + lcol + 8];
        uint4 bl0 = *(const uint4*)&Bl[(size_t)(n0 + lrow) * ldb + k0 + lcol];
        uint4 bl1 = *(const uint4*)&Bl[(size_t)(n0 + lrow) * ldb + k0 + lcol + 8];
        if (afp32) {
            float4 f[4];
#pragma unroll
            for (int q = 0; q < 4; q++)
                f[q] = *(const float4*)&Af[(size_t)(m0 + lrow) * lda + k0 + lcol + q * 4];
            __syncthreads();
#pragma unroll
            for (int q = 0; q < 4; q++) {
                float vv[4] = {f[q].x, f[q].y, f[q].z, f[q].w};
#pragma unroll
                for (int e = 0; e < 4; e++) {
                    __nv_bfloat16 h, l;
                    splitbf(vv[e], h, l);
                    sAh[lrow][lcol + q * 4 + e] = h;
                    sAl[lrow][lcol + q * 4 + e] = l;
                }
            }
        } else {
            uint4 ah0 = *(const uint4*)&Ah[(size_t)(m0 + lrow) * lda + k0 + lcol];
            uint4 ah1 = *(const uint4*)&Ah[(size_t)(m0 + lrow) * lda + k0 + lcol + 8];
            uint4 al0 = *(const uint4*)&Al[(size_t)(m0 + lrow) * lda + k0 + lcol];
            uint4 al1 = *(const uint4*)&Al[(size_t)(m0 + lrow) * lda + k0 + lcol + 8];
            __syncthreads();
            *(uint4*)&sAh[lrow][lcol] = ah0; *(uint4*)&sAh[lrow][lcol + 8] = ah1;
            *(uint4*)&sAl[lrow][lcol] = al0; *(uint4*)&sAl[lrow][lcol + 8] = al1;
        }
        *(uint4*)&sBh[lrow][lcol] = bh0; *(uint4*)&sBh[lrow][lcol + 8] = bh1;
        *(uint4*)&sBl[lrow][lcol] = bl0; *(uint4*)&sBl[lrow][lcol + 8] = bl1;
        __syncthreads();

#pragma unroll
        for (int ks = 0; ks < 32; ks += 16) {
            uint32 aH[2][4], aL[2][4];
#pragma unroll
            for (int mt = 0; mt < 2; mt++) {
                int row = wm * 32 + mt * 16 + (lane & 15);
                int col = ks + (lane >> 4) * 8;
                ldm4(aH[mt], smaddr(&sAh[row][col]));
                ldm4(aL[mt], smaddr(&sAl[row][col]));
            }
            uint32 bH[8][2], bL[8][2];
#pragma unroll
            for (int np = 0; np < 4; np++) {
                int row = wn * 64 + np * 16 + (lane & 7) + ((lane >> 4) & 1) * 8;
                int col = ks + ((lane >> 3) & 1) * 8;
                uint32 t4[4];
                ldm4(t4, smaddr(&sBh[row][col]));
                bH[2*np][0] = t4[0]; bH[2*np][1] = t4[1];
                bH[2*np+1][0] = t4[2]; bH[2*np+1][1] = t4[3];
                ldm4(t4, smaddr(&sBl[row][col]));
                bL[2*np][0] = t4[0]; bL[2*np][1] = t4[1];
                bL[2*np+1][0] = t4[2]; bL[2*np+1][1] = t4[3];
            }
#pragma unroll
            for (int mt = 0; mt < 2; mt++)
#pragma unroll
                for (int nt = 0; nt < 8; nt++) {
                    mma16816(acc[mt][nt], aH[mt], bH[nt]);
                    mma16816(acc[mt][nt], aH[mt], bL[nt]);
                    mma16816(acc[mt][nt], aL[mt], bH[nt]);
                }
        }
    }

#pragma unroll
    for (int mt = 0; mt < 2; mt++) {
#pragma unroll
        for (int nt = 0; nt < 8; nt++) {
#pragma unroll
            for (int q = 0; q < 4; q++) {
                int m = m0 + wm * 32 + mt * 16 + (lane >> 2) + (q >> 1) * 8;
                int n = n0 + wn * 64 + nt * 8 + 2 * (lane & 3) + (q & 1);
                float v = acc[mt][nt][q] + bias[n];
                if (bias2) v += bias2[n];
                if (mode == 0) {
                    g_nextkc[m * CN + n] = v;
                } else if (mode == 1) {
                    int pr = g_perm[m];
                    __nv_bfloat16 h, l;
                    splitbf(v, h, l);
                    g_pch[(size_t)pr * CN + n] = h;
                    g_pcl[(size_t)pr * CN + n] = l;
                } else if (mode == 2) {
                    int orig = g_inv[m];
                    if (orig >= 0) {
                        int b = orig / TT, t = orig - b * TT;
                        g_G[((size_t)t * BB + b) * G4 + n] = v;
                    }
                } else {
                    Cext[(size_t)m * CN + n] = v;
                }
            }
        }
    }
}

// ---------------------------------------------------------------------------
// grid barrier: single-counter arrive (atomicAdd) + acquire-load poll by
// thread 0. Measured best across three barrier variants.
// ---------------------------------------------------------------------------
__device__ __forceinline__ void gsync(unsigned target) {
    __syncthreads();
    if (threadIdx.x == 0) {
        __threadfence();
        atomicAdd(&g_barc, 1u);
        unsigned v;
        do {
            asm volatile("ld.acquire.gpu.global.u32 %0, [%1];" : "=r"(v) : "l"(&g_barc));
        } while (v < target);
    }
    __syncthreads();
}

// ---------------------------------------------------------------------------
// Persistent fused LSTM — register-resident W_hh fragments with
// software-pipelined A fragments (R13 configuration, measured fastest).
// ---------------------------------------------------------------------------
__global__ __launch_bounds__(256, 1) void lstm_persist(const float* __restrict__ Whh) {
    extern __shared__ char smraw[];
    __nv_bfloat16* whh_h = (__nv_bfloat16*)smraw;           // staging (init only)
    __nv_bfloat16* whh_l = whh_h + 32 * WHP;
    float* part = (float*)smraw;                             // [8][64][PSTR] after init

    const int tid = threadIdx.x, wid = tid >> 5, lane = tid & 31;
    const int jb0 = blockIdx.x * 8;

    // ---- stage Whh slice (hi/lo) into smem ----
    for (int idx = tid; idx < 32 * 1024; idx += 256) {
        int c = idx >> 10, k = idx & 1023;
        int gr = ((c >> 3) << 10) + jb0 + (c & 7);
        float w = Whh[(size_t)gr * HH + k];
        __nv_bfloat16 h, l;
        splitbf(w, h, l);
        whh_h[c * WHP + k] = h;
        whh_l[c * WHP + k] = l;
    }
    __syncthreads();

    // ---- extract B fragments into registers (persistent) ----
    uint32 BH[8][4][2], BL[8][4][2];
#pragma unroll
    for (int kbl = 0; kbl < 8; kbl++) {
#pragma unroll
        for (int g = 0; g < 2; g++) {
            int row = g * 16 + (lane & 7) + ((lane >> 4) & 1) * 8;
            int col = (wid * 8 + kbl) * 16 + ((lane >> 3) & 1) * 8;
            uint32 t4[4];
            ldm4(t4, smaddr(&whh_h[row * WHP + col]));
            BH[kbl][2*g][0] = t4[0]; BH[kbl][2*g][1] = t4[1];
            BH[kbl][2*g+1][0] = t4[2]; BH[kbl][2*g+1][1] = t4[3];
            ldm4(t4, smaddr(&whh_l[row * WHP + col]));
            BL[kbl][2*g][0] = t4[0]; BL[kbl][2*g][1] = t4[1];
            BL[kbl][2*g+1][0] = t4[2]; BL[kbl][2*g+1][1] = t4[3];
        }
    }
    __syncthreads();   // staging area now reusable as partials

    // gate-thread constants
    const int gb_b = tid >> 2;
    const int gjp = tid & 3;
    const int m16w = gb_b >> 4;
    const int roww = gb_b & 15;
    const int rlw = roww & 7;
    const int regbase = (roww >> 3) + ((jb0 & 8) ? 2 : 0);
    const int k16w = jb0 >> 4;
    float cst2[2] = {0.f, 0.f};

    float gb[4][2];
    {
        const float* Gp = g_G + (size_t)gb_b * G4 + jb0 + 2 * gjp;
#pragma unroll
        for (int g = 0; g < 4; g++) {
            float2 v = __ldcg((const float2*)&Gp[g * HH]);
            gb[g][0] = v.x; gb[g][1] = v.y;
        }
    }

    for (int t = 0; t < TT; t++) {
        const uint32* fH = g_hfrag[t & 1][0];
        const uint32* fL = g_hfrag[t & 1][1];
        const int nb = (t + 1) & 1;

        float acc[4][4][4];
#pragma unroll
        for (int mf = 0; mf < 4; mf++)
#pragma unroll
            for (int nf = 0; nf < 4; nf++)
#pragma unroll
                for (int q = 0; q < 4; q++) acc[mf][nf][q] = 0.f;

        // preload kbl 0's aH
        uint4 aH4[2][4], aL4[4];
        {
            const int kb = wid * 8;
#pragma unroll
            for (int mf = 0; mf < 4; mf++)
                aH4[0][mf] = __ldcg((const uint4*)&fH[((kb * 4 + mf) * 32 + lane) * 4]);
        }

#pragma unroll
        for (int kbl = 0; kbl < 8; kbl++) {
            const int cur = kbl & 1, nxt = cur ^ 1;
            const int kb = wid * 8 + kbl;
            // issue current aL + next aH before the mma block
#pragma unroll
            for (int mf = 0; mf < 4; mf++)
                aL4[mf] = __ldcg((const uint4*)&fL[((kb * 4 + mf) * 32 + lane) * 4]);
            if (kbl < 7) {
#pragma unroll
                for (int mf = 0; mf < 4; mf++)
                    aH4[nxt][mf] = __ldcg((const uint4*)&fH[(((kb + 1) * 4 + mf) * 32 + lane) * 4]);
            }
#pragma unroll
            for (int mf = 0; mf < 4; mf++)
#pragma unroll
                for (int nf = 0; nf < 4; nf++) {
                    mma16816(acc[mf][nf], (const uint32*)&aH4[cur][mf], BH[kbl][nf]);
                    mma16816(acc[mf][nf], (const uint32*)&aH4[cur][mf], BL[kbl][nf]);
                }
#pragma unroll
            for (int mf = 0; mf < 4; mf++)
#pragma unroll
                for (int nf = 0; nf < 4; nf++)
                    mma16816(acc[mf][nf], (const uint32*)&aL4[mf], BH[kbl][nf]);
        }

        // STS partials
        {
            float* pw = part + wid * (64 * PSTR);
            int rowc = lane >> 2, colc = (lane & 3) * 2;
#pragma unroll
            for (int mf = 0; mf < 4; mf++)
#pragma unroll
                for (int nf = 0; nf < 4; nf++) {
                    int n = nf * 8 + colc;
                    *(float2*)&pw[(mf * 16 + rowc) * PSTR + n] =
                        make_float2(acc[mf][nf][0], acc[mf][nf][1]);
                    *(float2*)&pw[(mf * 16 + rowc + 8) * PSTR + n] =
                        make_float2(acc[mf][nf][2], acc[mf][nf][3]);
                }
        }
        __syncthreads();

        // gates: all 256 threads
        {
            float zz[4][2];
#pragma unroll
            for (int g = 0; g < 4; g++) { zz[g][0] = 0.f; zz[g][1] = 0.f; }
#pragma unroll
            for (int w8 = 0; w8 < 8; w8++) {
                const float* pr = part + w8 * (64 * PSTR) + gb_b * PSTR + 2 * gjp;
#pragma unroll
                for (int g = 0; g < 4; g++) {
                    float2 v = *(const float2*)&pr[g * 8];
                    zz[g][0] += v.x; zz[g][1] += v.y;
                }
            }
            unsigned short hh[2], hl[2];
#pragma unroll
            for (int e = 0; e < 2; e++) {
                float pi = zz[0][e] + gb[0][e];
                float pf = zz[1][e] + gb[1][e];
                float pg = zz[2][e] + gb[2][e];
                float po = zz[3][e] + gb[3][e];
                float iv = 1.f / (1.f + expf(-pi));
                float fv = 1.f / (1.f + expf(-pf));
                float ov = 1.f / (1.f + expf(-po));
                float gv = tanhf(pg);
                cst2[e] = fv * cst2[e] + iv * gv;
                float h = ov * tanhf(cst2[e]);
                __nv_bfloat16 bh, bl;
                splitbf(h, bh, bl);
                hh[e] = __bfloat16_as_ushort(bh);
                hl[e] = __bfloat16_as_ushort(bl);
            }
            uint32 vh = (uint32)hh[0] | ((uint32)hh[1] << 16);
            uint32 vl = (uint32)hl[0] | ((uint32)hl[1] << 16);
            int idx = ((k16w * 4 + m16w) * 32 + rlw * 4 + gjp) * 4 + regbase;
            g_hfrag[nb][0][idx] = vh;
            g_hfrag[nb][1][idx] = vl;
            *(uint32*)&g_hsh[((size_t)gb_b * TT + t) * HH + jb0 + 2 * gjp] = vh;
            *(uint32*)&g_hsl[((size_t)gb_b * TT + t) * HH + jb0 + 2 * gjp] = vl;
        }

        if (t + 1 < TT) {
            const float* Gp = g_G + ((size_t)(t + 1) * BB + gb_b) * G4 + jb0 + 2 * gjp;
#pragma unroll
            for (int g = 0; g < 4; g++) {
                float2 v = __ldcg((const float2*)&Gp[g * HH]);
                gb[g][0] = v.x; gb[g][1] = v.y;
            }
        }

        gsync((unsigned)(t + 1) * NCTA);
    }
}

// ---------------------------------------------------------------------------
__global__ void out_kernel(const float* __restrict__ Wout,
                           const float* __restrict__ bout,
                           float* __restrict__ dout) {
    int gw = (blockIdx.x * blockDim.x + threadIdx.x) >> 5;
    int lane = threadIdx.x & 31;
    if (gw >= MROWS) return;
    const float* stu = dout + MROWS + (size_t)gw * CN;
    float s = 0.f;
#pragma unroll
    for (int c = lane; c < CN; c += 32) {
        float nk = g_nextkc[gw * CN + c];
        s += (stu[c] - nk) * nk * Wout[c];
    }
#pragma unroll
    for (int o = 16; o; o >>= 1) s += __shfl_down_sync(0xffffffffu, s, o);
    if (lane == 0) dout[gw] = s + bout[0];
}

extern "C" void kernel_launch(void* const* d_in, const int* in_sizes, int n_in,
                              void* d_out, int out_size) {
    int wi = (n_in >= 14) ? 4 : 3;
    const float* q_hot   = (const float*)d_in[0];
    const int*   result  = (const int*)  d_in[1];
    const float* next_q  = (const float*)d_in[2];
    const float* W_kc    = (const float*)d_in[wi + 0];
    const float* b_kc    = (const float*)d_in[wi + 1];
    const float* W_ih    = (const float*)d_in[wi + 2];
    const float* W_hh    = (const float*)d_in[wi + 3];
    const float* b_ih    = (const float*)d_in[wi + 4];
    const float* b_hh    = (const float*)d_in[wi + 5];
    const float* W_state = (const float*)d_in[wi + 6];
    const float* b_state = (const float*)d_in[wi + 7];
    const float* W_out   = (const float*)d_in[wi + 8];
    const float* b_out   = (const float*)d_in[wi + 9];
    float* out = (float*)d_out;

    static int smem_set = 0;
    if (!smem_set) {
        cudaFuncSetAttribute(lstm_persist, cudaFuncAttributeMaxDynamicSharedMemorySize, SMEM_LSTM);
        smem_set = 1;
    }

    init_misc<<<(2 * FRAGW + 255) / 256, 256>>>();
    build_perm<<<1, 256>>>(result);

    __nv_bfloat16 *wkh, *wkl, *wih, *wil, *wsh, *wsl;
    cudaGetSymbolAddress((void**)&wkh, g_wkh); cudaGetSymbolAddress((void**)&wkl, g_wkl);
    cudaGetSymbolAddress((void**)&wih, g_wih); cudaGetSymbolAddress((void**)&wil, g_wil);
    cudaGetSymbolAddress((void**)&wsh, g_wsh); cudaGetSymbolAddress((void**)&wsl, g_wsl);

    int n4k = CN * NS / 4;
    cvt_split<<<(n4k + 255) / 256, 256>>>(W_kc, wkh, wkl, n4k);
    int n4i = G4 * 2 * CN / 4;
    cvt_split<<<(n4i + 255) / 256, 256>>>(W_ih, wih, wil, n4i);
    int n4s = CN * HH / 4;
    cvt_split<<<(n4s + 255) / 256, 256>>>(W_state, wsh, wsl, n4s);

    dim3 gk(CN / 128, MROWS / 128);       // (2, 100)
    // kc -> permuted planes (mode 1, fused fp32 split)
    mma_gemm<<<gk, 256>>>(q_hot, nullptr, wkh, wkl, b_kc, nullptr, nullptr,
                          NS, NS, NS, 1, 1);
    // next_kc (mode 0, fused fp32 split)
    mma_gemm<<<gk, 256>>>(next_q, nullptr, wkh, wkl, b_kc, nullptr, nullptr,
                          NS, NS, NS, 0, 1);
    // gx (mode 2)
    dim3 gg(G4 / 128, MPAD / 128);        // (32, 101)
    mma_gemm<<<gg, 256>>>(nullptr, nullptr, wih, wil, b_ih, b_hh, nullptr,
                          CN, CN, 2 * CN, 2, 0);

    lstm_persist<<<NCTA, 256, SMEM_LSTM>>>(W_hh);

    // stu_state (mode 3)
    mma_gemm<<<gk, 256>>>(nullptr, nullptr, wsh, wsl, b_state, nullptr,
                          out + MROWS, HH, HH, HH, 3, 0);
    out_kernel<<<(MROWS * 32 + 255) / 256, 256>>>(W_out, b_out, out);
}